// round 4
// baseline (speedup 1.0000x reference)
#include <cuda_runtime.h>
#include <cstdint>

// Problem dims (fixed by dataset)
#define BD   4
#define SD   2048
#define DD   4096
#define OD   4096
#define ED   8
#define RD   8
#define MD   (BD*SD)   // 8192
#define NER  64        // E*R
#define KTOT (DD+NER)  // 4160
#define SCALING 2.0f

// k_main tiling
#define TM 128
#define TN 256
#define KC 32                   // 32 floats = 128B row
#define NCHUNK (KTOT/KC)        // 130
#define STAGE_BYTES 49152u      // A 16K + B 32K
#define NSTAGE 3
#define SMEM_MAIN (NSTAGE * STAGE_BYTES)   // 147456

// Scratch (device globals)
__device__ float g_part[BD * 8 * DD];
__device__ float g_weights[BD * ED];
__device__ float gx[MD * DD];      // tf32(x)
__device__ float gw[OD * DD];      // tf32(W_base)
__device__ float g_hw[MD * NER];   // tf32(scaled down-proj)
__device__ float g_lbt[OD * NER];  // tf32(lora_B transposed to [n][er])

// ---------------- helpers ----------------
__device__ __forceinline__ uint32_t smem_u32(const void* p) {
    uint32_t a;
    asm("{ .reg .u64 t; cvta.to.shared.u64 t, %1; cvt.u32.u64 %0, t; }" : "=r"(a) : "l"(p));
    return a;
}
__device__ __forceinline__ uint32_t f2tf32(float f) {
    uint32_t u;
    asm("cvt.rna.tf32.f32 %0, %1;" : "=r"(u) : "f"(f));
    return u;
}
__device__ __forceinline__ float f2tf32f(float f) { return __uint_as_float(f2tf32(f)); }
#define SW128(o) ((o) ^ (((o) >> 3) & 0x70))

__device__ __forceinline__ void ldsm4(uint32_t* r, uint32_t addr) {
    asm volatile("ldmatrix.sync.aligned.m8n8.x4.shared.b16 {%0,%1,%2,%3}, [%4];"
                 : "=r"(r[0]), "=r"(r[1]), "=r"(r[2]), "=r"(r[3]) : "r"(addr));
}
__device__ __forceinline__ void mma8(float* d, const uint32_t* a, uint32_t b0, uint32_t b1) {
    asm volatile("mma.sync.aligned.m16n8k8.row.col.f32.tf32.tf32.f32 "
                 "{%0,%1,%2,%3}, {%4,%5,%6,%7}, {%8,%9}, {%0,%1,%2,%3};"
                 : "+f"(d[0]), "+f"(d[1]), "+f"(d[2]), "+f"(d[3])
                 : "r"(a[0]), "r"(a[1]), "r"(a[2]), "r"(a[3]), "r"(b0), "r"(b1));
}
__device__ __forceinline__ void cp16(uint32_t s, const float* g) {
    asm volatile("cp.async.cg.shared.global [%0], [%1], 16;"
                 :: "r"(s), "l"((unsigned long long)__cvta_generic_to_global(g)) : "memory");
}
__device__ __forceinline__ void cp_commit() {
    asm volatile("cp.async.commit_group;" ::: "memory");
}
__device__ __forceinline__ void cp_wait1() {
    asm volatile("cp.async.wait_group 1;" ::: "memory");
}
__device__ __forceinline__ void cp_wait0() {
    asm volatile("cp.async.wait_group 0;" ::: "memory");
}

// ---------------------------------------------------------------------------
// K1: partial column sums over S (router input) + write tf32(x) to gx
// ---------------------------------------------------------------------------
__global__ void k_colsum(const float* __restrict__ x) {
    int d  = blockIdx.x * 256 + threadIdx.x;
    int sc = blockIdx.y;
    int b  = blockIdx.z;
    size_t base = ((size_t)b * SD + (size_t)sc * 256) * DD + d;
    const float* p = x + base;
    float* q = gx + base;
    float s0 = 0.f, s1 = 0.f;
    #pragma unroll 8
    for (int s = 0; s < 256; s += 2) {
        float v0 = p[(size_t)s * DD], v1 = p[(size_t)(s + 1) * DD];
        s0 += v0; s1 += v1;
        q[(size_t)s * DD]       = f2tf32f(v0);
        q[(size_t)(s + 1) * DD] = f2tf32f(v1);
    }
    g_part[((size_t)b * 8 + sc) * DD + d] = s0 + s1;
}

// K1b: convert W_base -> gw (tf32)
__global__ void k_convW(const float* __restrict__ Wb) {
    size_t i = ((size_t)blockIdx.x * 256 + threadIdx.x) * 4;
    float4 v = *(const float4*)(Wb + i);
    float4 t = { f2tf32f(v.x), f2tf32f(v.y), f2tf32f(v.z), f2tf32f(v.w) };
    *(float4*)(gw + i) = t;
}

// K1c: transpose lora_B [E,O,R] -> g_lbt [n][er] (tf32)
__global__ void k_convLB(const float* __restrict__ lB) {
    int n = blockIdx.x * 32 + (threadIdx.x >> 3);
    int e = threadIdx.x & 7;
    float4 v0 = *(const float4*)(lB + ((size_t)e * OD + n) * RD);
    float4 v1 = *(const float4*)(lB + ((size_t)e * OD + n) * RD + 4);
    float4 t0 = { f2tf32f(v0.x), f2tf32f(v0.y), f2tf32f(v0.z), f2tf32f(v0.w) };
    float4 t1 = { f2tf32f(v1.x), f2tf32f(v1.y), f2tf32f(v1.z), f2tf32f(v1.w) };
    *(float4*)(g_lbt + (size_t)n * NER + e * 8)     = t0;
    *(float4*)(g_lbt + (size_t)n * NER + e * 8 + 4) = t1;
}

// ---------------------------------------------------------------------------
// K2: router logits + softmax -> g_weights = SCALING * softmax
// ---------------------------------------------------------------------------
__global__ void k_router(const float* __restrict__ rW, const float* __restrict__ rb) {
    __shared__ float logits[BD * ED];
    int warp = threadIdx.x >> 5, lane = threadIdx.x & 31;
    for (int pair = warp; pair < BD * ED; pair += 8) {
        int b = pair >> 3, e = pair & 7;
        float acc = 0.f;
        for (int d = lane; d < DD; d += 32) {
            float cs = 0.f;
            #pragma unroll
            for (int c = 0; c < 8; c++) cs += g_part[((size_t)b * 8 + c) * DD + d];
            acc += cs * rW[(size_t)e * DD + d];
        }
        #pragma unroll
        for (int o = 16; o > 0; o >>= 1) acc += __shfl_xor_sync(0xffffffffu, acc, o);
        if (lane == 0) logits[pair] = acc * (1.0f / (float)SD) + rb[e];
    }
    __syncthreads();
    if (threadIdx.x < BD) {
        int b = threadIdx.x;
        float mx = -1e30f;
        #pragma unroll
        for (int e = 0; e < ED; e++) mx = fmaxf(mx, logits[b * ED + e]);
        float w[ED], sum = 0.f;
        #pragma unroll
        for (int e = 0; e < ED; e++) { w[e] = expf(logits[b * ED + e] - mx); sum += w[e]; }
        float inv = SCALING / sum;
        #pragma unroll
        for (int e = 0; e < ED; e++) g_weights[b * ED + e] = w[e] * inv;
    }
}

// ---------------------------------------------------------------------------
// K3: g_hw[m][er] = tf32( w[b][er/8] * sum_k gx[m][k]*lora_A[er][k] )
// tf32 mma.sync, CTA 128x64, 8 warps, warp tile 16x64, double-buffered SMEM.
// ---------------------------------------------------------------------------
#define HW_STAGE 24576u   // A 16K + B 8K
__global__ __launch_bounds__(256) void k_hw(const float* __restrict__ loraA) {
    extern __shared__ char smem[];
    uint32_t sbase = smem_u32(smem);
    int tid = threadIdx.x, lane = tid & 31, wid = tid >> 5;
    int mBase = blockIdx.x * 128;
    int wm = wid * 16;
    float acc[8][4] = {};

    int rA  = wm + (lane & 7) + ((lane >> 3) & 1) * 8;
    int cAb = ((lane >> 4) & 1) * 16;
    int rB  = (lane & 7) + ((lane >> 4) & 1) * 8;
    int cBb = ((lane >> 3) & 1) * 16;

    int sq = tid & 7, sr = tid >> 3;   // staging coords

    // register prefetch (A from gx already tf32, B from loraA with cvt)
    float4 pa[4]; float4 pb[2];
    auto ldg = [&](int k0) {
        #pragma unroll
        for (int p = 0; p < 4; p++)
            pa[p] = *(const float4*)(gx + (size_t)(mBase + sr + p * 32) * DD + k0 + 4 * sq);
        #pragma unroll
        for (int p = 0; p < 2; p++)
            pb[p] = *(const float4*)(loraA + (size_t)(sr + p * 32) * DD + k0 + 4 * sq);
    };
    ldg(0);

    for (int i = 0; i < DD / KC; i++) {
        uint32_t offA = (i & 1) * HW_STAGE;
        uint32_t offB = offA + 16384u;
        #pragma unroll
        for (int p = 0; p < 4; p++)
            *(float4*)(smem + offA + SW128((uint32_t)((sr + p * 32) * 128 + sq * 16))) = pa[p];
        #pragma unroll
        for (int p = 0; p < 2; p++) {
            float4 v = pb[p];
            uint4 t = { f2tf32(v.x), f2tf32(v.y), f2tf32(v.z), f2tf32(v.w) };
            *(uint4*)(smem + offB + SW128((uint32_t)((sr + p * 32) * 128 + sq * 16))) = t;
        }
        __syncthreads();
        if (i + 1 < DD / KC) ldg((i + 1) * KC);

        uint32_t aB = sbase + offA, bB = sbase + offB;
        #pragma unroll
        for (int ks = 0; ks < 4; ks++) {
            uint32_t af[4];
            ldsm4(af, aB + SW128((uint32_t)(rA * 128 + ks * 32 + cAb)));
            uint32_t bf[4][4];
            #pragma unroll
            for (int g = 0; g < 4; g++)
                ldsm4(bf[g], bB + SW128((uint32_t)((rB + g * 16) * 128 + ks * 32 + cBb)));
            #pragma unroll
            for (int g = 0; g < 4; g++) {
                mma8(acc[2 * g],     af, bf[g][0], bf[g][1]);
                mma8(acc[2 * g + 1], af, bf[g][2], bf[g][3]);
            }
        }
        __syncthreads();
    }

    int b = mBase >> 11;
    int m0 = mBase + wm + (lane >> 2);
    #pragma unroll
    for (int g = 0; g < 8; g++) {
        int er = g * 8 + 2 * (lane & 3);
        float sc = g_weights[b * ED + g];    // er..er+1 within expert g
        float2 v0 = { f2tf32f(acc[g][0] * sc), f2tf32f(acc[g][1] * sc) };
        float2 v1 = { f2tf32f(acc[g][2] * sc), f2tf32f(acc[g][3] * sc) };
        *(float2*)(g_hw + (size_t)m0 * NER + er)       = v0;
        *(float2*)(g_hw + (size_t)(m0 + 8) * NER + er) = v1;
    }
}

// ---------------------------------------------------------------------------
// K4: tf32 mma.sync main GEMM, augmented K, cp.async 3-stage pipeline.
// CTA 128x256, 8 warps (2m x 4n), warp tile 64x64.
// ---------------------------------------------------------------------------
__global__ __launch_bounds__(256, 1) void k_main_mma(const float* __restrict__ bb,
                                                     float* __restrict__ out) {
    extern __shared__ char smem[];
    uint32_t sbase = smem_u32(smem);

    int tid = threadIdx.x, lane = tid & 31, wid = tid >> 5;
    int wm = (wid & 1) * 64;
    int wn = (wid >> 1) * 64;
    int mBase = blockIdx.y * TM;
    int nBase = blockIdx.x * TN;

    float acc[4][8][4] = {};

    int rA  = wm + (lane & 7) + ((lane >> 3) & 1) * 8;
    int cAb = ((lane >> 4) & 1) * 16;
    int rB  = wn + (lane & 7) + ((lane >> 4) & 1) * 8;
    int cBb = ((lane >> 3) & 1) * 16;

    int sq = tid & 7, sr = tid >> 3;

    auto issue = [&](int i) {
        int k0 = i * KC;
        uint32_t stA = sbase + (uint32_t)(i % NSTAGE) * STAGE_BYTES;
        uint32_t stB = stA + 16384u;
        const float* srcA; const float* srcB; int strA, strB, col;
        if (k0 < DD) { srcA = gx + (size_t)mBase * DD;  strA = DD;
                       srcB = gw + (size_t)nBase * DD;  strB = DD;  col = k0; }
        else         { srcA = g_hw  + (size_t)mBase * NER; strA = NER;
                       srcB = g_lbt + (size_t)nBase * NER; strB = NER; col = k0 - DD; }
        #pragma unroll
        for (int p = 0; p < 4; p++) {
            int row = sr + p * 32;
            cp16(stA + SW128((uint32_t)(row * 128 + sq * 16)),
                 srcA + (size_t)row * strA + col + 4 * sq);
        }
        #pragma unroll
        for (int p = 0; p < 8; p++) {
            int row = sr + p * 32;
            cp16(stB + SW128((uint32_t)(row * 128 + sq * 16)),
                 srcB + (size_t)row * strB + col + 4 * sq);
        }
        cp_commit();
    };

    issue(0);
    issue(1);

    for (int i = 0; i < NCHUNK; i++) {
        if (i + 1 < NCHUNK) cp_wait1(); else cp_wait0();
        __syncthreads();
        if (i + 2 < NCHUNK) issue(i + 2);

        uint32_t aB = sbase + (uint32_t)(i % NSTAGE) * STAGE_BYTES;
        uint32_t bB = aB + 16384u;
        #pragma unroll
        for (int ks = 0; ks < 4; ks++) {
            uint32_t af[4][4];
            #pragma unroll
            for (int f = 0; f < 4; f++)
                ldsm4(af[f], aB + SW128((uint32_t)((rA + ((f & 1) ? 16 : 0) + ((f & 2) ? 32 : 0)) * 128 + ks * 32 + cAb)));
            uint32_t bf[4][4];
            #pragma unroll
            for (int g = 0; g < 4; g++)
                ldsm4(bf[g], bB + SW128((uint32_t)((rB + g * 16) * 128 + ks * 32 + cBb)));
            #pragma unroll
            for (int f = 0; f < 4; f++)
                #pragma unroll
                for (int g = 0; g < 4; g++) {
                    mma8(acc[f][2 * g],     af[f], bf[g][0], bf[g][1]);
                    mma8(acc[f][2 * g + 1], af[f], bf[g][2], bf[g][3]);
                }
        }
        __syncthreads();
    }

    // Epilogue: frag f covers rows wm + f*16; pairs at (m0, m0+8)
    #pragma unroll
    for (int f = 0; f < 4; f++) {
        int m0 = mBase + wm + f * 16 + (lane >> 2);
        #pragma unroll
        for (int g = 0; g < 8; g++) {
            int n = nBase + wn + g * 8 + 2 * (lane & 3);
            float b0 = bb[n], b1 = bb[n + 1];
            float2 v0 = { acc[f][g][0] + b0, acc[f][g][1] + b1 };
            float2 v1 = { acc[f][g][2] + b0, acc[f][g][3] + b1 };
            *(float2*)(out + (size_t)m0 * OD + n)       = v0;
            *(float2*)(out + (size_t)(m0 + 8) * OD + n) = v1;
        }
    }
}

// ---------------------------------------------------------------------------
extern "C" void kernel_launch(void* const* d_in, const int* in_sizes, int n_in,
                              void* d_out, int out_size) {
    const float* x   = (const float*)d_in[0];
    const float* Wb  = (const float*)d_in[1];
    const float* bbv = (const float*)d_in[2];
    const float* lA  = (const float*)d_in[3];
    const float* lB  = (const float*)d_in[4];
    const float* rW  = (const float*)d_in[5];
    const float* rb  = (const float*)d_in[6];
    float* out = (float*)d_out;

    cudaFuncSetAttribute(k_main_mma, cudaFuncAttributeMaxDynamicSharedMemorySize, SMEM_MAIN);
    cudaFuncSetAttribute(k_hw, cudaFuncAttributeMaxDynamicSharedMemorySize, 2 * HW_STAGE);

    k_colsum<<<dim3(DD / 256, 8, BD), 256>>>(x);
    k_convW<<<(OD * DD / 4) / 256, 256>>>(Wb);
    k_convLB<<<OD / 32, 256>>>(lB);
    k_router<<<1, 256>>>(rW, rb);
    k_hw<<<MD / 128, 256, 2 * HW_STAGE>>>(lA);
    k_main_mma<<<dim3(OD / TN, MD / TM), 256, SMEM_MAIN>>>(bbv, out);
}

// round 5
// speedup vs baseline: 1.3484x; 1.3484x over previous
#include <cuda_runtime.h>
#include <cstdint>

// Problem dims (fixed by dataset)
#define BD   4
#define SD   2048
#define DD   4096
#define OD   4096
#define ED   8
#define RD   8
#define MD   (BD*SD)   // 8192
#define NER  64        // E*R
#define KTOT (DD+NER)  // 4160
#define SCALING 2.0f

// k_main tiling: CTA 128x128, 8 warps (4m x 2n), warp tile 32x64
#define TM 128
#define TN 128
#define KC 32                   // 32 floats = 128B row
#define NCHUNK (KTOT/KC)        // 130
#define STAGE_BYTES 32768u      // A 16K + B 16K
#define NSTAGE 3
#define SMEM_MAIN (NSTAGE * STAGE_BYTES)   // 98304 -> 2 CTAs/SM

// Scratch (device globals)
__device__ float g_part[BD * 8 * DD];
__device__ float g_logits[BD * ED];
__device__ float g_weights[BD * ED];
__device__ float gx[MD * DD];      // tf32(x)
__device__ float gw[OD * DD];      // tf32(W_base)
__device__ float g_hw[MD * NER];   // tf32(scaled down-proj)
__device__ float g_lbt[OD * NER];  // tf32(lora_B transposed to [n][er])

// ---------------- helpers ----------------
__device__ __forceinline__ uint32_t smem_u32(const void* p) {
    uint32_t a;
    asm("{ .reg .u64 t; cvta.to.shared.u64 t, %1; cvt.u32.u64 %0, t; }" : "=r"(a) : "l"(p));
    return a;
}
__device__ __forceinline__ uint32_t f2tf32(float f) {
    uint32_t u;
    asm("cvt.rna.tf32.f32 %0, %1;" : "=r"(u) : "f"(f));
    return u;
}
__device__ __forceinline__ float f2tf32f(float f) { return __uint_as_float(f2tf32(f)); }
#define SW128(o) ((o) ^ (((o) >> 3) & 0x70))

__device__ __forceinline__ void ldsm4(uint32_t* r, uint32_t addr) {
    asm volatile("ldmatrix.sync.aligned.m8n8.x4.shared.b16 {%0,%1,%2,%3}, [%4];"
                 : "=r"(r[0]), "=r"(r[1]), "=r"(r[2]), "=r"(r[3]) : "r"(addr));
}
__device__ __forceinline__ void mma8(float* d, const uint32_t* a, uint32_t b0, uint32_t b1) {
    asm volatile("mma.sync.aligned.m16n8k8.row.col.f32.tf32.tf32.f32 "
                 "{%0,%1,%2,%3}, {%4,%5,%6,%7}, {%8,%9}, {%0,%1,%2,%3};"
                 : "+f"(d[0]), "+f"(d[1]), "+f"(d[2]), "+f"(d[3])
                 : "r"(a[0]), "r"(a[1]), "r"(a[2]), "r"(a[3]), "r"(b0), "r"(b1));
}
__device__ __forceinline__ void cp16(uint32_t s, const float* g) {
    asm volatile("cp.async.cg.shared.global [%0], [%1], 16;"
                 :: "r"(s), "l"((unsigned long long)__cvta_generic_to_global(g)) : "memory");
}
__device__ __forceinline__ void cp_commit() { asm volatile("cp.async.commit_group;" ::: "memory"); }
__device__ __forceinline__ void cp_wait1()  { asm volatile("cp.async.wait_group 1;" ::: "memory"); }
__device__ __forceinline__ void cp_wait0()  { asm volatile("cp.async.wait_group 0;" ::: "memory"); }

// ---------------------------------------------------------------------------
// K1: partial column sums over S (router input) + write tf32(x) to gx
// ---------------------------------------------------------------------------
__global__ void k_colsum(const float* __restrict__ x) {
    int d  = blockIdx.x * 256 + threadIdx.x;
    int sc = blockIdx.y;
    int b  = blockIdx.z;
    size_t base = ((size_t)b * SD + (size_t)sc * 256) * DD + d;
    const float* p = x + base;
    float* q = gx + base;
    float s0 = 0.f, s1 = 0.f, s2 = 0.f, s3 = 0.f;
    #pragma unroll 8
    for (int s = 0; s < 256; s += 4) {
        float v0 = p[(size_t)(s + 0) * DD], v1 = p[(size_t)(s + 1) * DD];
        float v2 = p[(size_t)(s + 2) * DD], v3 = p[(size_t)(s + 3) * DD];
        s0 += v0; s1 += v1; s2 += v2; s3 += v3;
        q[(size_t)(s + 0) * DD] = f2tf32f(v0);
        q[(size_t)(s + 1) * DD] = f2tf32f(v1);
        q[(size_t)(s + 2) * DD] = f2tf32f(v2);
        q[(size_t)(s + 3) * DD] = f2tf32f(v3);
    }
    g_part[((size_t)b * 8 + sc) * DD + d] = (s0 + s1) + (s2 + s3);
}

// K1b: convert W_base -> gw (tf32)
__global__ void k_convW(const float* __restrict__ Wb) {
    size_t i = ((size_t)blockIdx.x * 256 + threadIdx.x) * 4;
    float4 v = *(const float4*)(Wb + i);
    float4 t = { f2tf32f(v.x), f2tf32f(v.y), f2tf32f(v.z), f2tf32f(v.w) };
    *(float4*)(gw + i) = t;
}

// K1c: transpose lora_B [E,O,R] -> g_lbt [n][er] (tf32)
__global__ void k_convLB(const float* __restrict__ lB) {
    int n = blockIdx.x * 32 + (threadIdx.x >> 3);
    int e = threadIdx.x & 7;
    float4 v0 = *(const float4*)(lB + ((size_t)e * OD + n) * RD);
    float4 v1 = *(const float4*)(lB + ((size_t)e * OD + n) * RD + 4);
    float4 t0 = { f2tf32f(v0.x), f2tf32f(v0.y), f2tf32f(v0.z), f2tf32f(v0.w) };
    float4 t1 = { f2tf32f(v1.x), f2tf32f(v1.y), f2tf32f(v1.z), f2tf32f(v1.w) };
    *(float4*)(g_lbt + (size_t)n * NER + e * 8)     = t0;
    *(float4*)(g_lbt + (size_t)n * NER + e * 8 + 4) = t1;
}

// ---------------------------------------------------------------------------
// K2a: logits — one block per (b,e), 256 threads, block reduction
// ---------------------------------------------------------------------------
__global__ void k_logit(const float* __restrict__ rW, const float* __restrict__ rb) {
    __shared__ float red[8];
    int b = blockIdx.x >> 3, e = blockIdx.x & 7;
    int tid = threadIdx.x, lane = tid & 31, warp = tid >> 5;
    float acc = 0.f;
    for (int d = tid; d < DD; d += 256) {
        float cs = 0.f;
        #pragma unroll
        for (int c = 0; c < 8; c++) cs += g_part[((size_t)b * 8 + c) * DD + d];
        acc += cs * rW[(size_t)e * DD + d];
    }
    #pragma unroll
    for (int o = 16; o > 0; o >>= 1) acc += __shfl_xor_sync(0xffffffffu, acc, o);
    if (lane == 0) red[warp] = acc;
    __syncthreads();
    if (tid == 0) {
        float s = 0.f;
        #pragma unroll
        for (int w = 0; w < 8; w++) s += red[w];
        g_logits[blockIdx.x] = s * (1.0f / (float)SD) + rb[e];
    }
}

// K2b: softmax over 8 experts -> g_weights = SCALING * softmax
__global__ void k_softmax() {
    int b = threadIdx.x;
    if (b < BD) {
        float mx = -1e30f;
        #pragma unroll
        for (int e = 0; e < ED; e++) mx = fmaxf(mx, g_logits[b * ED + e]);
        float w[ED], sum = 0.f;
        #pragma unroll
        for (int e = 0; e < ED; e++) { w[e] = expf(g_logits[b * ED + e] - mx); sum += w[e]; }
        float inv = SCALING / sum;
        #pragma unroll
        for (int e = 0; e < ED; e++) g_weights[b * ED + e] = w[e] * inv;
    }
}

// ---------------------------------------------------------------------------
// K3: g_hw[m][er] = tf32( w[b][er/8] * sum_k gx[m][k]*lora_A[er][k] )
// tf32 mma.sync, CTA 128x64, 8 warps, warp tile 16x64, double-buffered SMEM.
// ---------------------------------------------------------------------------
#define HW_STAGE 24576u   // A 16K + B 8K
__global__ __launch_bounds__(256) void k_hw(const float* __restrict__ loraA) {
    extern __shared__ char smem[];
    uint32_t sbase = smem_u32(smem);
    int tid = threadIdx.x, lane = tid & 31, wid = tid >> 5;
    int mBase = blockIdx.x * 128;
    int wm = wid * 16;
    float acc[8][4] = {};

    int rA  = wm + (lane & 7) + ((lane >> 3) & 1) * 8;
    int cAb = ((lane >> 4) & 1) * 16;
    int rB  = (lane & 7) + ((lane >> 4) & 1) * 8;
    int cBb = ((lane >> 3) & 1) * 16;

    int sq = tid & 7, sr = tid >> 3;

    float4 pa[4]; float4 pb[2];
    auto ldg = [&](int k0) {
        #pragma unroll
        for (int p = 0; p < 4; p++)
            pa[p] = *(const float4*)(gx + (size_t)(mBase + sr + p * 32) * DD + k0 + 4 * sq);
        #pragma unroll
        for (int p = 0; p < 2; p++)
            pb[p] = *(const float4*)(loraA + (size_t)(sr + p * 32) * DD + k0 + 4 * sq);
    };
    ldg(0);

    for (int i = 0; i < DD / KC; i++) {
        uint32_t offA = (i & 1) * HW_STAGE;
        uint32_t offB = offA + 16384u;
        #pragma unroll
        for (int p = 0; p < 4; p++)
            *(float4*)(smem + offA + SW128((uint32_t)((sr + p * 32) * 128 + sq * 16))) = pa[p];
        #pragma unroll
        for (int p = 0; p < 2; p++) {
            float4 v = pb[p];
            uint4 t = { f2tf32(v.x), f2tf32(v.y), f2tf32(v.z), f2tf32(v.w) };
            *(uint4*)(smem + offB + SW128((uint32_t)((sr + p * 32) * 128 + sq * 16))) = t;
        }
        __syncthreads();
        if (i + 1 < DD / KC) ldg((i + 1) * KC);

        uint32_t aB = sbase + offA, bB = sbase + offB;
        #pragma unroll
        for (int ks = 0; ks < 4; ks++) {
            uint32_t af[4];
            ldsm4(af, aB + SW128((uint32_t)(rA * 128 + ks * 32 + cAb)));
            uint32_t bf[4][4];
            #pragma unroll
            for (int g = 0; g < 4; g++)
                ldsm4(bf[g], bB + SW128((uint32_t)((rB + g * 16) * 128 + ks * 32 + cBb)));
            #pragma unroll
            for (int g = 0; g < 4; g++) {
                mma8(acc[2 * g],     af, bf[g][0], bf[g][1]);
                mma8(acc[2 * g + 1], af, bf[g][2], bf[g][3]);
            }
        }
        __syncthreads();
    }

    int b = mBase >> 11;
    int m0 = mBase + wm + (lane >> 2);
    #pragma unroll
    for (int g = 0; g < 8; g++) {
        int er = g * 8 + 2 * (lane & 3);
        float sc = g_weights[b * ED + g];
        float2 v0 = { f2tf32f(acc[g][0] * sc), f2tf32f(acc[g][1] * sc) };
        float2 v1 = { f2tf32f(acc[g][2] * sc), f2tf32f(acc[g][3] * sc) };
        *(float2*)(g_hw + (size_t)m0 * NER + er)       = v0;
        *(float2*)(g_hw + (size_t)(m0 + 8) * NER + er) = v1;
    }
}

// ---------------------------------------------------------------------------
// K4: tf32 mma.sync main GEMM, augmented K, cp.async 3-stage, 2 CTAs/SM.
// CTA 128x128, 8 warps (4m x 2n), warp tile 32x64.
// ---------------------------------------------------------------------------
__global__ __launch_bounds__(256, 2) void k_main_mma(const float* __restrict__ bb,
                                                     float* __restrict__ out) {
    extern __shared__ char smem[];
    uint32_t sbase = smem_u32(smem);

    int tid = threadIdx.x, lane = tid & 31, wid = tid >> 5;
    int wm = (wid & 3) * 32;
    int wn = (wid >> 2) * 64;
    int mBase = blockIdx.y * TM;
    int nBase = blockIdx.x * TN;

    float acc[2][8][4] = {};

    int rA  = wm + (lane & 7) + ((lane >> 3) & 1) * 8;   // + f*16
    int cAb = ((lane >> 4) & 1) * 16;
    int rB  = wn + (lane & 7) + ((lane >> 4) & 1) * 8;   // + g*16
    int cBb = ((lane >> 3) & 1) * 16;

    int sq = tid & 7, sr = tid >> 3;

    auto issue = [&](int i) {
        int k0 = i * KC;
        uint32_t stA = sbase + (uint32_t)(i % NSTAGE) * STAGE_BYTES;
        uint32_t stB = stA + 16384u;
        const float* srcA; const float* srcB; int strA, strB, col;
        if (k0 < DD) { srcA = gx + (size_t)mBase * DD;  strA = DD;
                       srcB = gw + (size_t)nBase * DD;  strB = DD;  col = k0; }
        else         { srcA = g_hw  + (size_t)mBase * NER; strA = NER;
                       srcB = g_lbt + (size_t)nBase * NER; strB = NER; col = k0 - DD; }
        #pragma unroll
        for (int p = 0; p < 4; p++) {
            int row = sr + p * 32;
            uint32_t so = SW128((uint32_t)(row * 128 + sq * 16));
            cp16(stA + so, srcA + (size_t)row * strA + col + 4 * sq);
            cp16(stB + so, srcB + (size_t)row * strB + col + 4 * sq);
        }
        cp_commit();
    };

    issue(0);
    issue(1);

    for (int i = 0; i < NCHUNK; i++) {
        if (i + 1 < NCHUNK) cp_wait1(); else cp_wait0();
        __syncthreads();
        if (i + 2 < NCHUNK) issue(i + 2);

        uint32_t aB = sbase + (uint32_t)(i % NSTAGE) * STAGE_BYTES;
        uint32_t bB = aB + 16384u;
        #pragma unroll
        for (int ks = 0; ks < 4; ks++) {
            uint32_t af[2][4];
            #pragma unroll
            for (int f = 0; f < 2; f++)
                ldsm4(af[f], aB + SW128((uint32_t)((rA + f * 16) * 128 + ks * 32 + cAb)));
            uint32_t bf[4][4];
            #pragma unroll
            for (int g = 0; g < 4; g++)
                ldsm4(bf[g], bB + SW128((uint32_t)((rB + g * 16) * 128 + ks * 32 + cBb)));
            #pragma unroll
            for (int f = 0; f < 2; f++)
                #pragma unroll
                for (int g = 0; g < 4; g++) {
                    mma8(acc[f][2 * g],     af[f], bf[g][0], bf[g][1]);
                    mma8(acc[f][2 * g + 1], af[f], bf[g][2], bf[g][3]);
                }
        }
        __syncthreads();
    }

    #pragma unroll
    for (int f = 0; f < 2; f++) {
        int m0 = mBase + wm + f * 16 + (lane >> 2);
        #pragma unroll
        for (int g = 0; g < 8; g++) {
            int n = nBase + wn + g * 8 + 2 * (lane & 3);
            float b0 = bb[n], b1 = bb[n + 1];
            float2 v0 = { acc[f][g][0] + b0, acc[f][g][1] + b1 };
            float2 v1 = { acc[f][g][2] + b0, acc[f][g][3] + b1 };
            *(float2*)(out + (size_t)m0 * OD + n)       = v0;
            *(float2*)(out + (size_t)(m0 + 8) * OD + n) = v1;
        }
    }
}

// ---------------------------------------------------------------------------
extern "C" void kernel_launch(void* const* d_in, const int* in_sizes, int n_in,
                              void* d_out, int out_size) {
    const float* x   = (const float*)d_in[0];
    const float* Wb  = (const float*)d_in[1];
    const float* bbv = (const float*)d_in[2];
    const float* lA  = (const float*)d_in[3];
    const float* lB  = (const float*)d_in[4];
    const float* rW  = (const float*)d_in[5];
    const float* rb  = (const float*)d_in[6];
    float* out = (float*)d_out;

    cudaFuncSetAttribute(k_main_mma, cudaFuncAttributeMaxDynamicSharedMemorySize, SMEM_MAIN);
    cudaFuncSetAttribute(k_hw, cudaFuncAttributeMaxDynamicSharedMemorySize, 2 * HW_STAGE);

    k_colsum<<<dim3(DD / 256, 8, BD), 256>>>(x);
    k_convW<<<(OD * DD / 4) / 256, 256>>>(Wb);
    k_convLB<<<OD / 32, 256>>>(lB);
    k_logit<<<BD * ED, 256>>>(rW, rb);
    k_softmax<<<1, 32>>>();
    k_hw<<<MD / 128, 256, 2 * HW_STAGE>>>(lA);
    k_main_mma<<<dim3(OD / TN, MD / TM), 256, SMEM_MAIN>>>(bbv, out);
}

// round 6
// speedup vs baseline: 2.0475x; 1.5185x over previous
#include <cuda_runtime.h>
#include <cstdint>

// Problem dims (fixed by dataset)
#define BD   4
#define SD   2048
#define DD   4096
#define OD   4096
#define ED   8
#define RD   8
#define MD   (BD*SD)   // 8192
#define NER  64        // E*R
#define KTOT (DD+NER)  // 4160
#define SCALING 2.0f

// k_main tiling: CTA 128x128, 8 warps (4m x 2n), warp tile 32x64
#define TM 128
#define TN 128
#define KC 32
#define NCHUNK (KTOT/KC)        // 130
#define STAGE_BYTES 32768u      // A 16K + B 16K
#define NSTAGE 3
#define SMEM_MAIN (NSTAGE * STAGE_BYTES)   // 98304 -> 2 CTAs/SM

// Scratch (device globals)
__device__ float g_part[BD * 8 * DD];
__device__ float g_logits[BD * ED];
__device__ float gx[MD * DD];      // tf32(x)
__device__ float gw[OD * DD];      // tf32(W_base)
__device__ float g_hw[MD * NER];   // tf32(router-scaled down-proj)
__device__ float g_lbt[OD * NER];  // tf32(lora_B transposed to [n][er])

// ---------------- helpers ----------------
__device__ __forceinline__ uint32_t smem_u32(const void* p) {
    uint32_t a;
    asm("{ .reg .u64 t; cvta.to.shared.u64 t, %1; cvt.u32.u64 %0, t; }" : "=r"(a) : "l"(p));
    return a;
}
__device__ __forceinline__ uint32_t f2tf32(float f) {
    uint32_t u;
    asm("cvt.rna.tf32.f32 %0, %1;" : "=r"(u) : "f"(f));
    return u;
}
__device__ __forceinline__ float f2tf32f(float f) { return __uint_as_float(f2tf32(f)); }
#define SW128(o) ((o) ^ (((o) >> 3) & 0x70))

__device__ __forceinline__ void ldsm4(uint32_t* r, uint32_t addr) {
    asm volatile("ldmatrix.sync.aligned.m8n8.x4.shared.b16 {%0,%1,%2,%3}, [%4];"
                 : "=r"(r[0]), "=r"(r[1]), "=r"(r[2]), "=r"(r[3]) : "r"(addr));
}
__device__ __forceinline__ void mma8(float* d, const uint32_t* a, uint32_t b0, uint32_t b1) {
    asm volatile("mma.sync.aligned.m16n8k8.row.col.f32.tf32.tf32.f32 "
                 "{%0,%1,%2,%3}, {%4,%5,%6,%7}, {%8,%9}, {%0,%1,%2,%3};"
                 : "+f"(d[0]), "+f"(d[1]), "+f"(d[2]), "+f"(d[3])
                 : "r"(a[0]), "r"(a[1]), "r"(a[2]), "r"(a[3]), "r"(b0), "r"(b1));
}
__device__ __forceinline__ void cp16(uint32_t s, const float* g) {
    asm volatile("cp.async.cg.shared.global [%0], [%1], 16;"
                 :: "r"(s), "l"((unsigned long long)__cvta_generic_to_global(g)) : "memory");
}
__device__ __forceinline__ void cp_commit() { asm volatile("cp.async.commit_group;" ::: "memory"); }
__device__ __forceinline__ void cp_wait1()  { asm volatile("cp.async.wait_group 1;" ::: "memory"); }
__device__ __forceinline__ void cp_wait0()  { asm volatile("cp.async.wait_group 0;" ::: "memory"); }

// ---------------------------------------------------------------------------
// Launch 1: fused prep — colsum + tf32(x)->gx | tf32(W)->gw | lora_B -> g_lbt
// grid.x = 512 + 16384 + 128 = 17024 blocks of 256
// ---------------------------------------------------------------------------
__global__ void k_prep(const float* __restrict__ x, const float* __restrict__ Wb,
                       const float* __restrict__ lB) {
    int bid = blockIdx.x;
    if (bid < 512) {
        // colsum + gx: c = bid -> (dblk, sc, b)
        int d  = (bid & 15) * 256 + threadIdx.x;
        int sc = (bid >> 4) & 7;
        int b  = bid >> 7;
        size_t base = ((size_t)b * SD + (size_t)sc * 256) * DD + d;
        const float* p = x + base;
        float* q = gx + base;
        float s0 = 0.f, s1 = 0.f, s2 = 0.f, s3 = 0.f;
        #pragma unroll 8
        for (int s = 0; s < 256; s += 4) {
            float v0 = p[(size_t)(s + 0) * DD], v1 = p[(size_t)(s + 1) * DD];
            float v2 = p[(size_t)(s + 2) * DD], v3 = p[(size_t)(s + 3) * DD];
            s0 += v0; s1 += v1; s2 += v2; s3 += v3;
            q[(size_t)(s + 0) * DD] = f2tf32f(v0);
            q[(size_t)(s + 1) * DD] = f2tf32f(v1);
            q[(size_t)(s + 2) * DD] = f2tf32f(v2);
            q[(size_t)(s + 3) * DD] = f2tf32f(v3);
        }
        g_part[((size_t)b * 8 + sc) * DD + d] = (s0 + s1) + (s2 + s3);
    } else if (bid < 512 + 16384) {
        size_t i = ((size_t)(bid - 512) * 256 + threadIdx.x) * 4;
        float4 v = *(const float4*)(Wb + i);
        float4 t = { f2tf32f(v.x), f2tf32f(v.y), f2tf32f(v.z), f2tf32f(v.w) };
        *(float4*)(gw + i) = t;
    } else {
        int n = (bid - 512 - 16384) * 32 + (threadIdx.x >> 3);
        int e = threadIdx.x & 7;
        float4 v0 = *(const float4*)(lB + ((size_t)e * OD + n) * RD);
        float4 v1 = *(const float4*)(lB + ((size_t)e * OD + n) * RD + 4);
        float4 t0 = { f2tf32f(v0.x), f2tf32f(v0.y), f2tf32f(v0.z), f2tf32f(v0.w) };
        float4 t1 = { f2tf32f(v1.x), f2tf32f(v1.y), f2tf32f(v1.z), f2tf32f(v1.w) };
        *(float4*)(g_lbt + (size_t)n * NER + e * 8)     = t0;
        *(float4*)(g_lbt + (size_t)n * NER + e * 8 + 4) = t1;
    }
}

// ---------------------------------------------------------------------------
// Launch 2: logits — one block per (b,e), 256 threads, block reduction
// ---------------------------------------------------------------------------
__global__ void k_logit(const float* __restrict__ rW, const float* __restrict__ rb) {
    __shared__ float red[8];
    int b = blockIdx.x >> 3, e = blockIdx.x & 7;
    int tid = threadIdx.x, lane = tid & 31, warp = tid >> 5;
    float acc = 0.f;
    for (int d = tid; d < DD; d += 256) {
        float cs = 0.f;
        #pragma unroll
        for (int c = 0; c < 8; c++) cs += g_part[((size_t)b * 8 + c) * DD + d];
        acc += cs * rW[(size_t)e * DD + d];
    }
    #pragma unroll
    for (int o = 16; o > 0; o >>= 1) acc += __shfl_xor_sync(0xffffffffu, acc, o);
    if (lane == 0) red[warp] = acc;
    __syncthreads();
    if (tid == 0) {
        float s = 0.f;
        #pragma unroll
        for (int w = 0; w < 8; w++) s += red[w];
        g_logits[blockIdx.x] = s * (1.0f / (float)SD) + rb[e];
    }
}

// ---------------------------------------------------------------------------
// Launch 3: k_hw — g_hw[m][er] = tf32( softmax-weight * (gx @ lora_A^T) )
// CTA 128x64, warp tile 16x64, double-buffered, ONE barrier per chunk.
// Softmax computed inline from g_logits in the epilogue.
// ---------------------------------------------------------------------------
#define HW_STAGE 24576u   // A 16K + B 8K
__global__ __launch_bounds__(256) void k_hw(const float* __restrict__ loraA) {
    extern __shared__ char smem[];
    uint32_t sbase = smem_u32(smem);
    int tid = threadIdx.x, lane = tid & 31, wid = tid >> 5;
    int mBase = blockIdx.x * 128;
    int wm = wid * 16;
    float acc[8][4] = {};

    int rA  = wm + (lane & 7) + ((lane >> 3) & 1) * 8;
    int cAb = ((lane >> 4) & 1) * 16;
    int rB  = (lane & 7) + ((lane >> 4) & 1) * 8;
    int cBb = ((lane >> 3) & 1) * 16;

    int sq = tid & 7, sr = tid >> 3;

    float4 pa[4]; float4 pb[2];
    auto ldg = [&](int k0) {
        #pragma unroll
        for (int p = 0; p < 4; p++)
            pa[p] = *(const float4*)(gx + (size_t)(mBase + sr + p * 32) * DD + k0 + 4 * sq);
        #pragma unroll
        for (int p = 0; p < 2; p++)
            pb[p] = *(const float4*)(loraA + (size_t)(sr + p * 32) * DD + k0 + 4 * sq);
    };
    ldg(0);

    for (int i = 0; i < DD / KC; i++) {
        uint32_t offA = (i & 1) * HW_STAGE;
        uint32_t offB = offA + 16384u;
        #pragma unroll
        for (int p = 0; p < 4; p++)
            *(float4*)(smem + offA + SW128((uint32_t)((sr + p * 32) * 128 + sq * 16))) = pa[p];
        #pragma unroll
        for (int p = 0; p < 2; p++) {
            float4 v = pb[p];
            uint4 t = { f2tf32(v.x), f2tf32(v.y), f2tf32(v.z), f2tf32(v.w) };
            *(uint4*)(smem + offB + SW128((uint32_t)((sr + p * 32) * 128 + sq * 16))) = t;
        }
        __syncthreads();
        if (i + 1 < DD / KC) ldg((i + 1) * KC);

        uint32_t aB = sbase + offA, bB = sbase + offB;
        #pragma unroll
        for (int ks = 0; ks < 4; ks++) {
            uint32_t af[4];
            ldsm4(af, aB + SW128((uint32_t)(rA * 128 + ks * 32 + cAb)));
            uint32_t bf[4][4];
            #pragma unroll
            for (int g = 0; g < 4; g++)
                ldsm4(bf[g], bB + SW128((uint32_t)((rB + g * 16) * 128 + ks * 32 + cBb)));
            #pragma unroll
            for (int g = 0; g < 4; g++) {
                mma8(acc[2 * g],     af, bf[g][0], bf[g][1]);
                mma8(acc[2 * g + 1], af, bf[g][2], bf[g][3]);
            }
        }
        __syncthreads();   // required: next iter's STS targets the buffer just read
    }

    // inline softmax from logits (cheap, per-thread)
    int b = mBase >> 11;
    float lg[ED], mx = -1e30f;
    #pragma unroll
    for (int e = 0; e < ED; e++) { lg[e] = g_logits[b * ED + e]; mx = fmaxf(mx, lg[e]); }
    float sum = 0.f;
    #pragma unroll
    for (int e = 0; e < ED; e++) { lg[e] = expf(lg[e] - mx); sum += lg[e]; }
    float inv = SCALING / sum;

    int m0 = mBase + wm + (lane >> 2);
    #pragma unroll
    for (int g = 0; g < 8; g++) {
        int er = g * 8 + 2 * (lane & 3);
        float sc = lg[g] * inv;
        float2 v0 = { f2tf32f(acc[g][0] * sc), f2tf32f(acc[g][1] * sc) };
        float2 v1 = { f2tf32f(acc[g][2] * sc), f2tf32f(acc[g][3] * sc) };
        *(float2*)(g_hw + (size_t)m0 * NER + er)       = v0;
        *(float2*)(g_hw + (size_t)(m0 + 8) * NER + er) = v1;
    }
}

// ---------------------------------------------------------------------------
// Launch 4: k_main — tf32 mma.sync, augmented K, 3-stage cp.async,
// ONE barrier per chunk (top barrier also protects WAR on stage (i+2)%3).
// ---------------------------------------------------------------------------
__global__ __launch_bounds__(256, 2) void k_main_mma(const float* __restrict__ bb,
                                                     float* __restrict__ out) {
    extern __shared__ char smem[];
    uint32_t sbase = smem_u32(smem);

    int tid = threadIdx.x, lane = tid & 31, wid = tid >> 5;
    int wm = (wid & 3) * 32;
    int wn = (wid >> 2) * 64;
    int mBase = blockIdx.y * TM;
    int nBase = blockIdx.x * TN;

    float acc[2][8][4] = {};

    int rA  = wm + (lane & 7) + ((lane >> 3) & 1) * 8;
    int cAb = ((lane >> 4) & 1) * 16;
    int rB  = wn + (lane & 7) + ((lane >> 4) & 1) * 8;
    int cBb = ((lane >> 3) & 1) * 16;

    int sq = tid & 7, sr = tid >> 3;

    auto issue = [&](int i) {
        int k0 = i * KC;
        uint32_t stA = sbase + (uint32_t)(i % NSTAGE) * STAGE_BYTES;
        uint32_t stB = stA + 16384u;
        const float* srcA; const float* srcB; int strA, strB, col;
        if (k0 < DD) { srcA = gx + (size_t)mBase * DD;  strA = DD;
                       srcB = gw + (size_t)nBase * DD;  strB = DD;  col = k0; }
        else         { srcA = g_hw  + (size_t)mBase * NER; strA = NER;
                       srcB = g_lbt + (size_t)nBase * NER; strB = NER; col = k0 - DD; }
        #pragma unroll
        for (int p = 0; p < 4; p++) {
            int row = sr + p * 32;
            uint32_t so = SW128((uint32_t)(row * 128 + sq * 16));
            cp16(stA + so, srcA + (size_t)row * strA + col + 4 * sq);
            cp16(stB + so, srcB + (size_t)row * strB + col + 4 * sq);
        }
        cp_commit();
    };

    issue(0);
    issue(1);

    for (int i = 0; i < NCHUNK; i++) {
        if (i + 1 < NCHUNK) cp_wait1(); else cp_wait0();
        __syncthreads();        // data ready + all warps done with stage (i+2)%3
        if (i + 2 < NCHUNK) issue(i + 2);

        uint32_t aB = sbase + (uint32_t)(i % NSTAGE) * STAGE_BYTES;
        uint32_t bB = aB + 16384u;
        #pragma unroll
        for (int ks = 0; ks < 4; ks++) {
            uint32_t af[2][4];
            #pragma unroll
            for (int f = 0; f < 2; f++)
                ldsm4(af[f], aB + SW128((uint32_t)((rA + f * 16) * 128 + ks * 32 + cAb)));
            uint32_t bf[4][4];
            #pragma unroll
            for (int g = 0; g < 4; g++)
                ldsm4(bf[g], bB + SW128((uint32_t)((rB + g * 16) * 128 + ks * 32 + cBb)));
            #pragma unroll
            for (int f = 0; f < 2; f++)
                #pragma unroll
                for (int g = 0; g < 4; g++) {
                    mma8(acc[f][2 * g],     af[f], bf[g][0], bf[g][1]);
                    mma8(acc[f][2 * g + 1], af[f], bf[g][2], bf[g][3]);
                }
        }
        // no end-of-loop barrier: next top barrier protects WAR
    }

    #pragma unroll
    for (int f = 0; f < 2; f++) {
        int m0 = mBase + wm + f * 16 + (lane >> 2);
        #pragma unroll
        for (int g = 0; g < 8; g++) {
            int n = nBase + wn + g * 8 + 2 * (lane & 3);
            float b0 = bb[n], b1 = bb[n + 1];
            float2 v0 = { acc[f][g][0] + b0, acc[f][g][1] + b1 };
            float2 v1 = { acc[f][g][2] + b0, acc[f][g][3] + b1 };
            *(float2*)(out + (size_t)m0 * OD + n)       = v0;
            *(float2*)(out + (size_t)(m0 + 8) * OD + n) = v1;
        }
    }
}

// ---------------------------------------------------------------------------
extern "C" void kernel_launch(void* const* d_in, const int* in_sizes, int n_in,
                              void* d_out, int out_size) {
    const float* x   = (const float*)d_in[0];
    const float* Wb  = (const float*)d_in[1];
    const float* bbv = (const float*)d_in[2];
    const float* lA  = (const float*)d_in[3];
    const float* lB  = (const float*)d_in[4];
    const float* rW  = (const float*)d_in[5];
    const float* rb  = (const float*)d_in[6];
    float* out = (float*)d_out;

    cudaFuncSetAttribute(k_main_mma, cudaFuncAttributeMaxDynamicSharedMemorySize, SMEM_MAIN);
    cudaFuncSetAttribute(k_hw, cudaFuncAttributeMaxDynamicSharedMemorySize, 2 * HW_STAGE);

    k_prep<<<512 + 16384 + 128, 256>>>(x, Wb, lB);
    k_logit<<<BD * ED, 256>>>(rW, rb);
    k_hw<<<MD / 128, 256, 2 * HW_STAGE>>>(lA);
    k_main_mma<<<dim3(OD / TN, MD / TM), 256, SMEM_MAIN>>>(bbv, out);
}

// round 7
// speedup vs baseline: 2.2075x; 1.0781x over previous
#include <cuda_runtime.h>
#include <cstdint>

// Problem dims (fixed by dataset)
#define BD   4
#define SD   2048
#define DD   4096
#define OD   4096
#define ED   8
#define RD   8
#define MD   (BD*SD)   // 8192
#define NER  64        // E*R
#define KTOT (DD+NER)  // 4160
#define SCALING 2.0f

// k_main tiling: CTA 128x128, 8 warps (4m x 2n), warp tile 32x64
#define TM 128
#define TN 128
#define KC 32
#define NCHUNK (KTOT/KC)        // 130
#define STAGE_BYTES 32768u      // A 16K + B 16K
#define NSTAGE 3
#define SMEM_MAIN (NSTAGE * STAGE_BYTES)   // 98304 -> 2 CTAs/SM

// Scratch (device globals)
__device__ float g_part[BD * 8 * DD];
__device__ float g_logits[BD * ED];
__device__ float gx[MD * DD];      // tf32(x)
__device__ float gw[OD * DD];      // tf32(W_base)
__device__ float gla[NER * DD];    // tf32(lora_A) as [er][d]
__device__ float g_hw[MD * NER];   // tf32(router-scaled down-proj)
__device__ float g_lbt[OD * NER];  // tf32(lora_B transposed to [n][er])

// ---------------- helpers ----------------
__device__ __forceinline__ uint32_t smem_u32(const void* p) {
    uint32_t a;
    asm("{ .reg .u64 t; cvta.to.shared.u64 t, %1; cvt.u32.u64 %0, t; }" : "=r"(a) : "l"(p));
    return a;
}
__device__ __forceinline__ uint32_t f2tf32(float f) {
    uint32_t u;
    asm("cvt.rna.tf32.f32 %0, %1;" : "=r"(u) : "f"(f));
    return u;
}
__device__ __forceinline__ float f2tf32f(float f) { return __uint_as_float(f2tf32(f)); }
#define SW128(o) ((o) ^ (((o) >> 3) & 0x70))

__device__ __forceinline__ void ldsm4(uint32_t* r, uint32_t addr) {
    asm volatile("ldmatrix.sync.aligned.m8n8.x4.shared.b16 {%0,%1,%2,%3}, [%4];"
                 : "=r"(r[0]), "=r"(r[1]), "=r"(r[2]), "=r"(r[3]) : "r"(addr));
}
__device__ __forceinline__ void mma8(float* d, const uint32_t* a, uint32_t b0, uint32_t b1) {
    asm volatile("mma.sync.aligned.m16n8k8.row.col.f32.tf32.tf32.f32 "
                 "{%0,%1,%2,%3}, {%4,%5,%6,%7}, {%8,%9}, {%0,%1,%2,%3};"
                 : "+f"(d[0]), "+f"(d[1]), "+f"(d[2]), "+f"(d[3])
                 : "r"(a[0]), "r"(a[1]), "r"(a[2]), "r"(a[3]), "r"(b0), "r"(b1));
}
__device__ __forceinline__ void cp16(uint32_t s, const float* g) {
    asm volatile("cp.async.cg.shared.global [%0], [%1], 16;"
                 :: "r"(s), "l"((unsigned long long)__cvta_generic_to_global(g)) : "memory");
}
__device__ __forceinline__ void cp_commit() { asm volatile("cp.async.commit_group;" ::: "memory"); }
__device__ __forceinline__ void cp_wait1()  { asm volatile("cp.async.wait_group 1;" ::: "memory"); }
__device__ __forceinline__ void cp_wait0()  { asm volatile("cp.async.wait_group 0;" ::: "memory"); }

// ---------------------------------------------------------------------------
// Launch 1: fused prep
//   [0,512):          colsum + tf32(x) -> gx
//   [512,16896):      tf32(W_base) -> gw
//   [16896,17024):    lora_B -> g_lbt (transpose + tf32)
//   [17024,17280):    tf32(lora_A) -> gla
// ---------------------------------------------------------------------------
__global__ void k_prep(const float* __restrict__ x, const float* __restrict__ Wb,
                       const float* __restrict__ lB, const float* __restrict__ lA) {
    int bid = blockIdx.x;
    if (bid < 512) {
        int d  = (bid & 15) * 256 + threadIdx.x;
        int sc = (bid >> 4) & 7;
        int b  = bid >> 7;
        size_t base = ((size_t)b * SD + (size_t)sc * 256) * DD + d;
        const float* p = x + base;
        float* q = gx + base;
        float s0 = 0.f, s1 = 0.f, s2 = 0.f, s3 = 0.f;
        #pragma unroll 8
        for (int s = 0; s < 256; s += 4) {
            float v0 = p[(size_t)(s + 0) * DD], v1 = p[(size_t)(s + 1) * DD];
            float v2 = p[(size_t)(s + 2) * DD], v3 = p[(size_t)(s + 3) * DD];
            s0 += v0; s1 += v1; s2 += v2; s3 += v3;
            q[(size_t)(s + 0) * DD] = f2tf32f(v0);
            q[(size_t)(s + 1) * DD] = f2tf32f(v1);
            q[(size_t)(s + 2) * DD] = f2tf32f(v2);
            q[(size_t)(s + 3) * DD] = f2tf32f(v3);
        }
        g_part[((size_t)b * 8 + sc) * DD + d] = (s0 + s1) + (s2 + s3);
    } else if (bid < 512 + 16384) {
        size_t i = ((size_t)(bid - 512) * 256 + threadIdx.x) * 4;
        float4 v = *(const float4*)(Wb + i);
        float4 t = { f2tf32f(v.x), f2tf32f(v.y), f2tf32f(v.z), f2tf32f(v.w) };
        *(float4*)(gw + i) = t;
    } else if (bid < 512 + 16384 + 128) {
        int n = (bid - 512 - 16384) * 32 + (threadIdx.x >> 3);
        int e = threadIdx.x & 7;
        float4 v0 = *(const float4*)(lB + ((size_t)e * OD + n) * RD);
        float4 v1 = *(const float4*)(lB + ((size_t)e * OD + n) * RD + 4);
        float4 t0 = { f2tf32f(v0.x), f2tf32f(v0.y), f2tf32f(v0.z), f2tf32f(v0.w) };
        float4 t1 = { f2tf32f(v1.x), f2tf32f(v1.y), f2tf32f(v1.z), f2tf32f(v1.w) };
        *(float4*)(g_lbt + (size_t)n * NER + e * 8)     = t0;
        *(float4*)(g_lbt + (size_t)n * NER + e * 8 + 4) = t1;
    } else {
        size_t i = ((size_t)(bid - 512 - 16384 - 128) * 256 + threadIdx.x) * 4;
        float4 v = *(const float4*)(lA + i);
        float4 t = { f2tf32f(v.x), f2tf32f(v.y), f2tf32f(v.z), f2tf32f(v.w) };
        *(float4*)(gla + i) = t;
    }
}

// ---------------------------------------------------------------------------
// Launch 2: logits — one block per (b,e), 256 threads, block reduction
// ---------------------------------------------------------------------------
__global__ void k_logit(const float* __restrict__ rW, const float* __restrict__ rb) {
    __shared__ float red[8];
    int b = blockIdx.x >> 3, e = blockIdx.x & 7;
    int tid = threadIdx.x, lane = tid & 31, warp = tid >> 5;
    float acc = 0.f;
    for (int d = tid; d < DD; d += 256) {
        float cs = 0.f;
        #pragma unroll
        for (int c = 0; c < 8; c++) cs += g_part[((size_t)b * 8 + c) * DD + d];
        acc += cs * rW[(size_t)e * DD + d];
    }
    #pragma unroll
    for (int o = 16; o > 0; o >>= 1) acc += __shfl_xor_sync(0xffffffffu, acc, o);
    if (lane == 0) red[warp] = acc;
    __syncthreads();
    if (tid == 0) {
        float s = 0.f;
        #pragma unroll
        for (int w = 0; w < 8; w++) s += red[w];
        g_logits[blockIdx.x] = s * (1.0f / (float)SD) + rb[e];
    }
}

// ---------------------------------------------------------------------------
// Launch 3: k_hw v2 — g_hw[m][er] = tf32( softmax-weight * (gx @ gla^T) )
// CTA 64x64 (grid 128), 8 warps (4m x 2n), warp tile 16x32.
// cp.async 3-stage, ONE barrier per chunk. Softmax inline from g_logits.
// ---------------------------------------------------------------------------
#define HW_STAGE 16384u                       // A 8K + B 8K
#define HW_SMEM  (3u * HW_STAGE)              // 49152
__global__ __launch_bounds__(256) void k_hw(float* __restrict__ dummy) {
    extern __shared__ char smem[];
    uint32_t sbase = smem_u32(smem);
    int tid = threadIdx.x, lane = tid & 31, wid = tid >> 5;
    int mBase = blockIdx.x * 64;
    int wm = (wid & 3) * 16;
    int wn = (wid >> 2) * 32;
    float acc[4][4] = {};

    int rA  = wm + (lane & 7) + ((lane >> 3) & 1) * 8;
    int cAb = ((lane >> 4) & 1) * 16;
    int rB  = wn + (lane & 7) + ((lane >> 4) & 1) * 8;
    int cBb = ((lane >> 3) & 1) * 16;

    int sq = tid & 7, sr = tid >> 3;   // sr in [0,32)

    auto issue = [&](int i) {
        int k0 = i * KC;
        uint32_t stA = sbase + (uint32_t)(i % 3) * HW_STAGE;
        uint32_t stB = stA + 8192u;
        #pragma unroll
        for (int p = 0; p < 2; p++) {
            int row = sr + p * 32;
            uint32_t so = SW128((uint32_t)(row * 128 + sq * 16));
            cp16(stA + so, gx  + (size_t)(mBase + row) * DD + k0 + 4 * sq);
            cp16(stB + so, gla + (size_t)row * DD + k0 + 4 * sq);
        }
        cp_commit();
    };

    issue(0);
    issue(1);

    for (int i = 0; i < DD / KC; i++) {
        if (i + 1 < DD / KC) cp_wait1(); else cp_wait0();
        __syncthreads();
        if (i + 2 < DD / KC) issue(i + 2);

        uint32_t aB = sbase + (uint32_t)(i % 3) * HW_STAGE;
        uint32_t bB = aB + 8192u;
        #pragma unroll
        for (int ks = 0; ks < 4; ks++) {
            uint32_t af[4];
            ldsm4(af, aB + SW128((uint32_t)(rA * 128 + ks * 32 + cAb)));
            uint32_t bf[2][4];
            #pragma unroll
            for (int g = 0; g < 2; g++)
                ldsm4(bf[g], bB + SW128((uint32_t)((rB + g * 16) * 128 + ks * 32 + cBb)));
            #pragma unroll
            for (int g = 0; g < 2; g++) {
                mma8(acc[2 * g],     af, bf[g][0], bf[g][1]);
                mma8(acc[2 * g + 1], af, bf[g][2], bf[g][3]);
            }
        }
    }

    // inline softmax from logits
    int b = mBase >> 11;
    float lg[ED], mx = -1e30f;
    #pragma unroll
    for (int e = 0; e < ED; e++) { lg[e] = g_logits[b * ED + e]; mx = fmaxf(mx, lg[e]); }
    float sum = 0.f;
    #pragma unroll
    for (int e = 0; e < ED; e++) { lg[e] = expf(lg[e] - mx); sum += lg[e]; }
    float inv = SCALING / sum;

    int m0 = mBase + wm + (lane >> 2);
    #pragma unroll
    for (int g = 0; g < 4; g++) {
        int er = wn + g * 8 + 2 * (lane & 3);
        float sc = lg[er >> 3] * inv;
        float2 v0 = { f2tf32f(acc[g][0] * sc), f2tf32f(acc[g][1] * sc) };
        float2 v1 = { f2tf32f(acc[g][2] * sc), f2tf32f(acc[g][3] * sc) };
        *(float2*)(g_hw + (size_t)m0 * NER + er)       = v0;
        *(float2*)(g_hw + (size_t)(m0 + 8) * NER + er) = v1;
    }
}

// ---------------------------------------------------------------------------
// Launch 4: k_main — tf32 mma.sync, augmented K, 3-stage cp.async,
// ONE barrier per chunk.
// ---------------------------------------------------------------------------
__global__ __launch_bounds__(256, 2) void k_main_mma(const float* __restrict__ bb,
                                                     float* __restrict__ out) {
    extern __shared__ char smem[];
    uint32_t sbase = smem_u32(smem);

    int tid = threadIdx.x, lane = tid & 31, wid = tid >> 5;
    int wm = (wid & 3) * 32;
    int wn = (wid >> 2) * 64;
    int mBase = blockIdx.y * TM;
    int nBase = blockIdx.x * TN;

    float acc[2][8][4] = {};

    int rA  = wm + (lane & 7) + ((lane >> 3) & 1) * 8;
    int cAb = ((lane >> 4) & 1) * 16;
    int rB  = wn + (lane & 7) + ((lane >> 4) & 1) * 8;
    int cBb = ((lane >> 3) & 1) * 16;

    int sq = tid & 7, sr = tid >> 3;

    auto issue = [&](int i) {
        int k0 = i * KC;
        uint32_t stA = sbase + (uint32_t)(i % NSTAGE) * STAGE_BYTES;
        uint32_t stB = stA + 16384u;
        const float* srcA; const float* srcB; int strA, strB, col;
        if (k0 < DD) { srcA = gx + (size_t)mBase * DD;  strA = DD;
                       srcB = gw + (size_t)nBase * DD;  strB = DD;  col = k0; }
        else         { srcA = g_hw  + (size_t)mBase * NER; strA = NER;
                       srcB = g_lbt + (size_t)nBase * NER; strB = NER; col = k0 - DD; }
        #pragma unroll
        for (int p = 0; p < 4; p++) {
            int row = sr + p * 32;
            uint32_t so = SW128((uint32_t)(row * 128 + sq * 16));
            cp16(stA + so, srcA + (size_t)row * strA + col + 4 * sq);
            cp16(stB + so, srcB + (size_t)row * strB + col + 4 * sq);
        }
        cp_commit();
    };

    issue(0);
    issue(1);

    for (int i = 0; i < NCHUNK; i++) {
        if (i + 1 < NCHUNK) cp_wait1(); else cp_wait0();
        __syncthreads();        // data ready + all warps done with stage (i+2)%3
        if (i + 2 < NCHUNK) issue(i + 2);

        uint32_t aB = sbase + (uint32_t)(i % NSTAGE) * STAGE_BYTES;
        uint32_t bB = aB + 16384u;
        #pragma unroll
        for (int ks = 0; ks < 4; ks++) {
            uint32_t af[2][4];
            #pragma unroll
            for (int f = 0; f < 2; f++)
                ldsm4(af[f], aB + SW128((uint32_t)((rA + f * 16) * 128 + ks * 32 + cAb)));
            uint32_t bf[4][4];
            #pragma unroll
            for (int g = 0; g < 4; g++)
                ldsm4(bf[g], bB + SW128((uint32_t)((rB + g * 16) * 128 + ks * 32 + cBb)));
            #pragma unroll
            for (int f = 0; f < 2; f++)
                #pragma unroll
                for (int g = 0; g < 4; g++) {
                    mma8(acc[f][2 * g],     af[f], bf[g][0], bf[g][1]);
                    mma8(acc[f][2 * g + 1], af[f], bf[g][2], bf[g][3]);
                }
        }
    }

    #pragma unroll
    for (int f = 0; f < 2; f++) {
        int m0 = mBase + wm + f * 16 + (lane >> 2);
        #pragma unroll
        for (int g = 0; g < 8; g++) {
            int n = nBase + wn + g * 8 + 2 * (lane & 3);
            float b0 = bb[n], b1 = bb[n + 1];
            float2 v0 = { acc[f][g][0] + b0, acc[f][g][1] + b1 };
            float2 v1 = { acc[f][g][2] + b0, acc[f][g][3] + b1 };
            *(float2*)(out + (size_t)m0 * OD + n)       = v0;
            *(float2*)(out + (size_t)(m0 + 8) * OD + n) = v1;
        }
    }
}

// ---------------------------------------------------------------------------
extern "C" void kernel_launch(void* const* d_in, const int* in_sizes, int n_in,
                              void* d_out, int out_size) {
    const float* x   = (const float*)d_in[0];
    const float* Wb  = (const float*)d_in[1];
    const float* bbv = (const float*)d_in[2];
    const float* lA  = (const float*)d_in[3];
    const float* lB  = (const float*)d_in[4];
    const float* rW  = (const float*)d_in[5];
    const float* rb  = (const float*)d_in[6];
    float* out = (float*)d_out;

    cudaFuncSetAttribute(k_main_mma, cudaFuncAttributeMaxDynamicSharedMemorySize, SMEM_MAIN);
    cudaFuncSetAttribute(k_hw, cudaFuncAttributeMaxDynamicSharedMemorySize, HW_SMEM);

    k_prep<<<512 + 16384 + 128 + 256, 256>>>(x, Wb, lB, lA);
    k_logit<<<BD * ED, 256>>>(rW, rb);
    k_hw<<<MD / 64, 256, HW_SMEM>>>(nullptr);
    k_main_mma<<<dim3(OD / TN, MD / TM), 256, SMEM_MAIN>>>(bbv, out);
}